// round 17
// baseline (speedup 1.0000x reference)
#include <cuda_runtime.h>
#include <cuda_fp16.h>
#include <cstdint>
#include <cstddef>

#define B_  256
#define H_  512
#define E_  512
#define V_  32000
#define HW_ 256
#define F_  512
#define NB_ 250

typedef unsigned long long ull;

// Scratch (device globals)
__device__ float g_ht[B_ * H_];
__device__ float g_msum4[4 * B_ * HW_];
__device__ float g_gp[3 * B_ * 2048];
__device__ float g_pm[B_ * NB_];
__device__ float g_ps[B_ * NB_];
__device__ __half g_flat16[B_ * F_ * HW_];
__device__ __half g_wf16[H_ * F_];
__device__ __half g_wo_h[(size_t)V_ * H_];
__device__ __half g_h16[B_ * H_];
__device__ __half g_xh[B_ * 1536];
__device__ __half g_xl[B_ * 1536];
__device__ __half g_wc_h[2048 * 1536];
__device__ __half g_wc_l[2048 * 1536];

__device__ __forceinline__ ull pk2(float lo, float hi) {
    ull r; asm("mov.b64 %0, {%1, %2};" : "=l"(r) : "f"(lo), "f"(hi)); return r;
}
__device__ __forceinline__ float2 upk2(ull v) {
    float2 f; asm("mov.b64 {%0, %1}, %2;" : "=f"(f.x), "=f"(f.y) : "l"(v)); return f;
}
__device__ __forceinline__ void fma2(ull& d, ull a, ull b) {
    asm("fma.rn.f32x2 %0, %1, %2, %0;" : "+l"(d) : "l"(a), "l"(b));
}
__device__ __forceinline__ float tanha(float x) {
    float y; asm("tanh.approx.f32 %0, %1;" : "=f"(y) : "f"(x)); return y;
}
__device__ __forceinline__ void onl(float& m, float& s, float v) {
    if (v > m) { s = s * expf(m - v) + 1.f; m = v; }
    else       { s += expf(v - m); }
}

#define LDSM_X4(r0, r1, r2, r3, a)                                            \
    asm volatile("ldmatrix.sync.aligned.m8n8.x4.shared.b16 {%0,%1,%2,%3}, [%4];" \
                 : "=r"(r0), "=r"(r1), "=r"(r2), "=r"(r3) : "r"(a))
#define LDSM_X4T(r0, r1, r2, r3, a)                                           \
    asm volatile("ldmatrix.sync.aligned.m8n8.x4.trans.shared.b16 {%0,%1,%2,%3}, [%4];" \
                 : "=r"(r0), "=r"(r1), "=r"(r2), "=r"(r3) : "r"(a))
#define MMA_F16(d, a, b)                                                      \
    asm volatile("mma.sync.aligned.m16n8k16.row.col.f32.f16.f16.f32 "          \
                 "{%0,%1,%2,%3},{%4,%5,%6,%7},{%8,%9},{%0,%1,%2,%3};"          \
                 : "+f"((d)[0]), "+f"((d)[1]), "+f"((d)[2]), "+f"((d)[3])      \
                 : "r"((a)[0]), "r"((a)[1]), "r"((a)[2]), "r"((a)[3]),         \
                   "r"((b)[0]), "r"((b)[1]))
#define CP16(dst, src)                                                        \
    asm volatile("cp.async.cg.shared.global [%0], [%1], 16;" :: "r"(dst), "l"(src))
#define CPCOMMIT() asm volatile("cp.async.commit_group;")
template<int N> __device__ __forceinline__ void cp_wait() {
    asm volatile("cp.async.wait_group %0;" :: "n"(N));
}

// ---------------------------------------------------------------------------
// P1: main-stream prep (flat + Wf — attn's dependencies)
// ---------------------------------------------------------------------------
#define N_FLAT (B_ * F_ * HW_ / 4)
#define NWF4   (H_ * F_ / 4)
#define N_PREPM (N_FLAT + NWF4)

__global__ __launch_bounds__(256) void k_prep_main(const float* __restrict__ img,
                                                   const float* __restrict__ Wf) {
    int i = blockIdx.x * blockDim.x + threadIdx.x;
    if (i < N_FLAT) {
        float4 v = ((const float4*)img)[i];
        __half2* d = (__half2*)g_flat16;
        d[i * 2] = __floats2half2_rn(v.x, v.y);
        d[i * 2 + 1] = __floats2half2_rn(v.z, v.w);
        return;
    }
    i -= N_FLAT;
    if (i < NWF4) {
        float4 v = ((const float4*)Wf)[i];
        __half2* d = (__half2*)g_wf16;
        d[i * 2] = __floats2half2_rn(v.x, v.y);
        d[i * 2 + 1] = __floats2half2_rn(v.z, v.w);
    }
}

// ---------------------------------------------------------------------------
// P2: side prep (Wc hi/lo + Wo + tok/hid parts of x) — under attn
// ---------------------------------------------------------------------------
#define NWC4 (2048 * 1536 / 4)
#define NWO4 (V_ * H_ / 4)
#define NX4  (B_ * 1024 / 4)
#define N_PREPS (NWC4 + NWO4 + NX4)

__global__ __launch_bounds__(256) void k_prep_side(const float* __restrict__ Wih,
                                                   const float* __restrict__ Whh,
                                                   const float* __restrict__ Wo,
                                                   const float* __restrict__ tok,
                                                   const float* __restrict__ hid) {
    int i = blockIdx.x * blockDim.x + threadIdx.x;
    if (i < NWC4) {
        int jp = i * 4;
        int n = jp / 1536, k = jp - n * 1536;
        float4 v = (k < 1024) ? ((const float4*)(Wih + n * 1024 + k))[0]
                              : ((const float4*)(Whh + n * 512 + k - 1024))[0];
        __half2 h0 = __floats2half2_rn(v.x, v.y);
        __half2 h1 = __floats2half2_rn(v.z, v.w);
        float2 f0 = __half22float2(h0), f1 = __half22float2(h1);
        __half2* dh = (__half2*)g_wc_h;
        __half2* dl = (__half2*)g_wc_l;
        dh[i * 2] = h0;
        dh[i * 2 + 1] = h1;
        dl[i * 2] = __floats2half2_rn(v.x - f0.x, v.y - f0.y);
        dl[i * 2 + 1] = __floats2half2_rn(v.z - f1.x, v.w - f1.y);
        return;
    }
    i -= NWC4;
    if (i < NWO4) {
        float4 v = ((const float4*)Wo)[i];
        __half2* d = (__half2*)g_wo_h;
        d[i * 2] = __floats2half2_rn(v.x, v.y);
        d[i * 2 + 1] = __floats2half2_rn(v.z, v.w);
        return;
    }
    i -= NWO4;
    if (i < NX4) {
        int b = i >> 8, r = i & 255;   // 256 float4 per batch: 128 tok | 128 hid
        float4 v;
        int xo;
        if (r < 128) { v = ((const float4*)(tok + b * 512))[r]; xo = b * 1536 + r * 4; }
        else { v = ((const float4*)(hid + b * 512))[r - 128]; xo = b * 1536 + 1024 + (r - 128) * 4; }
        __half2 h0 = __floats2half2_rn(v.x, v.y);
        __half2 h1 = __floats2half2_rn(v.z, v.w);
        float2 f0 = __half22float2(h0), f1 = __half22float2(h1);
        *(__half2*)(g_xh + xo) = h0;
        *(__half2*)(g_xh + xo + 2) = h1;
        *(__half2*)(g_xl + xo) = __floats2half2_rn(v.x - f0.x, v.y - f0.y);
        *(__half2*)(g_xl + xo + 2) = __floats2half2_rn(v.z - f1.x, v.w - f1.y);
    }
}

// ---------------------------------------------------------------------------
// K1: g_ht = hidden @ W_h_w^T + W_h_b + W_F_b (f32x2) — side stream
// ---------------------------------------------------------------------------
__global__ __launch_bounds__(256) void k_ht(const float* __restrict__ A,
                                            const float* __restrict__ W,
                                            const float* __restrict__ b1,
                                            const float* __restrict__ b2) {
    __shared__ __align__(16) float As[32][68];
    __shared__ __align__(16) float Bs[32][68];
    const int tid = threadIdx.x;
    const int tx = tid & 15, ty = tid >> 4;
    const int m0 = blockIdx.y * 64, n0 = blockIdx.x * 64;
    ull acc[4][2] = {};
    for (int k0 = 0; k0 < H_; k0 += 32) {
        for (int idx = tid; idx < 64 * 32; idx += 256) {
            int k = idx & 31, m = idx >> 5;
            As[k][m] = A[(m0 + m) * H_ + k0 + k];
        }
        for (int idx = tid; idx < 64 * 32; idx += 256) {
            int k = idx & 31, n = idx >> 5;
            Bs[k][n] = W[(n0 + n) * H_ + k0 + k];
        }
        __syncthreads();
#pragma unroll 8
        for (int k = 0; k < 32; k++) {
            float4 av = *(const float4*)&As[k][ty * 4];
            ulonglong2 bq = *(const ulonglong2*)&Bs[k][tx * 4];
            float a[4] = {av.x, av.y, av.z, av.w};
            ull bb[2] = {bq.x, bq.y};
#pragma unroll
            for (int i = 0; i < 4; i++) {
                ull a2 = pk2(a[i], a[i]);
#pragma unroll
                for (int j = 0; j < 2; j++) fma2(acc[i][j], a2, bb[j]);
            }
        }
        __syncthreads();
    }
#pragma unroll
    for (int i = 0; i < 4; i++) {
        int m = m0 + ty * 4 + i;
#pragma unroll
        for (int j = 0; j < 2; j++) {
            int n = n0 + tx * 4 + j * 2;
            float2 v = upk2(acc[i][j]);
            g_ht[m * H_ + n] = v.x + b1[n] + b2[n];
            g_ht[m * H_ + n + 1] = v.y + b1[n + 1] + b2[n + 1];
        }
    }
}

// ---------------------------------------------------------------------------
// K2: attention scores. K=32, 16 stages, depth-5 (frozen)
// ---------------------------------------------------------------------------
#define AT_ST 18944
#define AT_B  8704
#define AT_SMEM (5 * AT_ST)

__global__ __launch_bounds__(256, 2) void k_attn_f16() {
    extern __shared__ __align__(16) unsigned char dsm[];
    const uint32_t sb = (uint32_t)__cvta_generic_to_shared(dsm);
    float* red = (float*)dsm;
    const int tid = threadIdx.x;
    const int lane = tid & 31, wid = tid >> 5;
    const int wm = wid & 1, wn = wid >> 1;
    const int g = lane >> 2, q = lane & 3;
    const int b = blockIdx.y, i0 = blockIdx.x * 128;
    const int h0 = blockIdx.z * 128;
    const __half* flatB = g_flat16 + (size_t)b * F_ * HW_ + i0;
    const float* htB = g_ht + b * H_;

    const int a_kr = ((lane >> 4) << 3) + (lane & 7);
    const int a_mc = ((lane >> 3) & 1) << 3;
    const int b_r = ((lane >> 4) << 3) + (lane & 7);
    const int b_c = lane & 8;
    const int fa = tid >> 4, ia = (tid & 15) << 3;
    const int hb = tid >> 2, fb = (tid & 3) << 3;

    float acc[4][4][4];
#pragma unroll
    for (int mf = 0; mf < 4; mf++)
#pragma unroll
        for (int nf = 0; nf < 4; nf++)
#pragma unroll
            for (int c = 0; c < 4; c++) acc[mf][nf][c] = 0.f;

    auto fill = [&](int s, int st) {
        const int f0 = s * 32;
#pragma unroll
        for (int p = 0; p < 2; p++) {
            int f = fa + p * 16;
            CP16(sb + st * AT_ST + ((f * 136 + ia) << 1),
                 flatB + (size_t)(f0 + f) * HW_ + ia);
        }
#pragma unroll
        for (int p = 0; p < 2; p++) {
            int h = hb + p * 64;
            CP16(sb + st * AT_ST + AT_B + ((h * 40 + fb) << 1),
                 g_wf16 + (size_t)(h0 + h) * F_ + f0 + fb);
        }
        CPCOMMIT();
    };

    fill(0, 0); fill(1, 1); fill(2, 2); fill(3, 3);
    for (int s = 0; s < 16; s++) {
        if (s <= 12) cp_wait<3>();
        else if (s == 13) cp_wait<2>();
        else if (s == 14) cp_wait<1>();
        else cp_wait<0>();
        __syncthreads();
        if (s + 4 < 16) fill(s + 4, (s + 4) % 5);
        const int buf = s % 5;
#pragma unroll
        for (int ks = 0; ks < 2; ks++) {
            uint32_t a[4][4], bb[4][2];
#pragma unroll
            for (int mf = 0; mf < 4; mf++) {
                uint32_t addr = sb + buf * AT_ST +
                    (((ks * 16 + a_kr) * 136 + wm * 64 + mf * 16 + a_mc) << 1);
                LDSM_X4T(a[mf][0], a[mf][1], a[mf][2], a[mf][3], addr);
            }
#pragma unroll
            for (int np = 0; np < 2; np++) {
                uint32_t addr = sb + buf * AT_ST + AT_B +
                    (((wn * 32 + np * 16 + b_r) * 40 + ks * 16 + b_c) << 1);
                LDSM_X4(bb[np * 2][0], bb[np * 2][1],
                        bb[np * 2 + 1][0], bb[np * 2 + 1][1], addr);
            }
#pragma unroll
            for (int mf = 0; mf < 4; mf++)
#pragma unroll
                for (int nf = 0; nf < 4; nf++) MMA_F16(acc[mf][nf], a[mf], bb[nf]);
        }
    }
    float ssum[8] = {};
#pragma unroll
    for (int mf = 0; mf < 4; mf++)
#pragma unroll
        for (int nf = 0; nf < 4; nf++) {
            int col = h0 + wn * 32 + nf * 8 + q * 2;
            float h0v = htB[col], h1v = htB[col + 1];
            ssum[mf * 2]     += tanha(h0v + acc[mf][nf][0]) + tanha(h1v + acc[mf][nf][1]);
            ssum[mf * 2 + 1] += tanha(h0v + acc[mf][nf][2]) + tanha(h1v + acc[mf][nf][3]);
        }
    __syncthreads();
#pragma unroll
    for (int mf = 0; mf < 4; mf++) {
        red[(wm * 64 + mf * 16 + g) * 17 + wn * 4 + q] = ssum[mf * 2];
        red[(wm * 64 + mf * 16 + g + 8) * 17 + wn * 4 + q] = ssum[mf * 2 + 1];
    }
    __syncthreads();
    if (tid < 128) {
        float s = 0.f;
#pragma unroll
        for (int x = 0; x < 16; x++) s += red[tid * 17 + x];
        g_msum4[(size_t)blockIdx.z * (B_ * HW_) + b * HW_ + i0 + tid] = s;
    }
}

// ---------------------------------------------------------------------------
// K3: context (full-chip, int4 loads) + writes ctx slice of g_xh/g_xl
// ---------------------------------------------------------------------------
__global__ __launch_bounds__(256) void k_ctx() {
    const int b = blockIdx.y, t = threadIdx.x;
    const int wid = t >> 5, lane = t & 31;
    const int f0 = blockIdx.x * 64;
    __shared__ float at[256];
    __shared__ float sm[256];
    const int o = b * HW_ + t;
    float v = (g_msum4[o] + g_msum4[B_ * HW_ + o] +
               g_msum4[2 * B_ * HW_ + o] + g_msum4[3 * B_ * HW_ + o]) *
              (1.0f / 51.2f);
    sm[t] = v;
    __syncthreads();
    for (int s = 128; s > 0; s >>= 1) {
        if (t < s) sm[t] = fmaxf(sm[t], sm[t + s]);
        __syncthreads();
    }
    float mx = sm[0];
    __syncthreads();
    float e = expf(v - mx);
    sm[t] = e;
    __syncthreads();
    for (int s = 128; s > 0; s >>= 1) {
        if (t < s) sm[t] += sm[t + s];
        __syncthreads();
    }
    at[t] = e / sm[0];
    __syncthreads();
    const uint4* base4 = (const uint4*)(g_flat16 + (size_t)b * F_ * HW_);
    for (int j = 0; j < 8; j++) {
        int f = f0 + j * 8 + wid;
        uint4 u = base4[(size_t)f * 32 + lane];
        const __half2* h2 = (const __half2*)&u;
        float s = 0.f;
        const float* aw = at + lane * 8;
#pragma unroll
        for (int p = 0; p < 4; p++) {
            float2 rv = __half22float2(h2[p]);
            s += aw[p * 2] * rv.x + aw[p * 2 + 1] * rv.y;
        }
#pragma unroll
        for (int o2 = 16; o2 > 0; o2 >>= 1) s += __shfl_xor_sync(0xffffffffu, s, o2);
        if (lane == 0) {
            __half hi = __float2half(s);
            int xo = b * 1536 + 512 + f;
            g_xh[xo] = hi;
            g_xl[xo] = __float2half(s - __half2float(hi));
        }
    }
}

// ---------------------------------------------------------------------------
// K5: gates GEMM, 3-term split-fp16, parametrized K slice.
// kb = kb_base + blockIdx.z * 512; partial slot = kb/512.
// ---------------------------------------------------------------------------
#define GA_ST 30720
#define GA_SMEM 92160

__global__ __launch_bounds__(256, 2) void k_gates_f16(int kb_base, int kb_step) {
    extern __shared__ __align__(16) unsigned char dsm[];
    const uint32_t sb = (uint32_t)__cvta_generic_to_shared(dsm);
    const int tid = threadIdx.x;
    const int lane = tid & 31, wid = tid >> 5;
    const int wm = wid & 1, wn = wid >> 1;
    const int g = lane >> 2, q = lane & 3;
    const int n0 = blockIdx.x * 128, m0 = blockIdx.y * 64;
    const int kb = kb_base + blockIdx.z * kb_step;

    const int a_r = lane & 15, a_c = (lane >> 4) << 3;
    const int b_r = ((lane >> 4) << 3) + (lane & 7), b_c = lane & 8;
    const int ra = tid >> 2, kc = (tid & 3) << 3;
    const int rr = tid >> 2;

    float acc[2][4][4];
#pragma unroll
    for (int mf = 0; mf < 2; mf++)
#pragma unroll
        for (int nf = 0; nf < 4; nf++)
#pragma unroll
            for (int c = 0; c < 4; c++) acc[mf][nf][c] = 0.f;

    auto fill2 = [&](int s, int st) {
        const int kk = kb + s * 32 + kc;
        uint32_t offa = (uint32_t)st * GA_ST + ((ra * 40 + kc) << 1);
        CP16(sb + offa, g_xh + (size_t)(m0 + ra) * 1536 + kk);
        CP16(sb + offa + 5120, g_xl + (size_t)(m0 + ra) * 1536 + kk);
#pragma unroll
        for (int p = 0; p < 2; p++) {
            int r = rr + p * 64;
            uint32_t offb = (uint32_t)st * GA_ST + 10240 + ((r * 40 + kc) << 1);
            CP16(sb + offb, g_wc_h + (size_t)(n0 + r) * 1536 + kk);
            CP16(sb + offb + 10240, g_wc_l + (size_t)(n0 + r) * 1536 + kk);
        }
        CPCOMMIT();
    };

    fill2(0, 0);
    fill2(1, 1);
    for (int s = 0; s < 16; s++) {
        if (s < 15) cp_wait<1>(); else cp_wait<0>();
        __syncthreads();
        if (s + 2 < 16) fill2(s + 2, (s + 2) % 3);
        const int buf = s % 3;
#pragma unroll
        for (int ks = 0; ks < 2; ks++) {
            uint32_t ah[2][4], al[2][4], bh[4][2], bl[4][2];
#pragma unroll
            for (int mf = 0; mf < 2; mf++) {
                uint32_t roff = ((wm * 32 + mf * 16 + a_r) * 40 + ks * 16 + a_c) << 1;
                LDSM_X4(ah[mf][0], ah[mf][1], ah[mf][2], ah[mf][3],
                        sb + buf * GA_ST + roff);
                LDSM_X4(al[mf][0], al[mf][1], al[mf][2], al[mf][3],
                        sb + buf * GA_ST + 5120 + roff);
            }
#pragma unroll
            for (int np = 0; np < 2; np++) {
                uint32_t roff = ((wn * 32 + np * 16 + b_r) * 40 + ks * 16 + b_c) << 1;
                LDSM_X4(bh[np * 2][0], bh[np * 2][1],
                        bh[np * 2 + 1][0], bh[np * 2 + 1][1],
                        sb + buf * GA_ST + 10240 + roff);
                LDSM_X4(bl[np * 2][0], bl[np * 2][1],
                        bl[np * 2 + 1][0], bl[np * 2 + 1][1],
                        sb + buf * GA_ST + 20480 + roff);
            }
#pragma unroll
            for (int mf = 0; mf < 2; mf++)
#pragma unroll
                for (int nf = 0; nf < 4; nf++) {
                    MMA_F16(acc[mf][nf], ah[mf], bh[nf]);
                    MMA_F16(acc[mf][nf], al[mf], bh[nf]);
                    MMA_F16(acc[mf][nf], ah[mf], bl[nf]);
                }
        }
    }
    float* gp = g_gp + (size_t)(kb >> 9) * (B_ * 2048);
#pragma unroll
    for (int mf = 0; mf < 2; mf++) {
        int row = m0 + wm * 32 + mf * 16 + g;
#pragma unroll
        for (int nf = 0; nf < 4; nf++) {
            int col = n0 + wn * 32 + nf * 8 + q * 2;
            *(float2*)&gp[(size_t)row * 2048 + col] =
                make_float2(acc[mf][nf][0], acc[mf][nf][1]);
            *(float2*)&gp[(size_t)(row + 8) * 2048 + col] =
                make_float2(acc[mf][nf][2], acc[mf][nf][3]);
        }
    }
}

// ---------------------------------------------------------------------------
// K6: LSTM pointwise
// ---------------------------------------------------------------------------
__global__ __launch_bounds__(256) void k_lstm(const float* __restrict__ cell,
                                              const float* __restrict__ bih,
                                              const float* __restrict__ bhh,
                                              float* __restrict__ hnew,
                                              float* __restrict__ cnew) {
    const int idx = blockIdx.x * blockDim.x + threadIdx.x;
    if (idx >= B_ * H_) return;
    const int b = idx >> 9, h = idx & 511;
    const int S = B_ * 2048;
    const int base = b * 2048;
    float pre[4];
#pragma unroll
    for (int gi = 0; gi < 4; gi++) {
        int n = gi * 512 + h;
        pre[gi] = g_gp[base + n] + g_gp[S + base + n] + g_gp[2 * S + base + n] +
                  bih[n] + bhh[n];
    }
    float ig = 1.f / (1.f + expf(-pre[0]));
    float fg = 1.f / (1.f + expf(-pre[1]));
    float gg = tanhf(pre[2]);
    float og = 1.f / (1.f + expf(-pre[3]));
    float c = fg * cell[idx] + ig * gg;
    cnew[idx] = c;
    float hn = og * tanhf(c);
    hnew[idx] = hn;
    g_h16[idx] = __float2half(hn);
}

// ---------------------------------------------------------------------------
// K7: vocab GEMM + fused softmax partials. K=32, 16 stages, depth-5 (frozen)
// ---------------------------------------------------------------------------
#define VO_ST 20480
#define VO_B  10240
#define VO_SMEM (5 * VO_ST)

__global__ __launch_bounds__(256, 2) void k_out_f16(const float* __restrict__ bias,
                                                    float* __restrict__ out) {
    extern __shared__ __align__(16) unsigned char dsm[];
    const uint32_t sb = (uint32_t)__cvta_generic_to_shared(dsm);
    const int tid = threadIdx.x;
    const int lane = tid & 31, wid = tid >> 5;
    const int wm = wid & 1, wn = wid >> 1;
    const int g = lane >> 2, q = lane & 3;
    const int nb = blockIdx.x;
    const int n0 = nb * 128, m0 = blockIdx.y * 128;

    const int a_r = lane & 15, a_c = (lane >> 4) << 3;
    const int b_r = ((lane >> 4) << 3) + (lane & 7), b_c = lane & 8;
    const int fr = tid >> 1, fsg = tid & 1;

    float acc[4][4][4];
#pragma unroll
    for (int mf = 0; mf < 4; mf++)
#pragma unroll
        for (int nf = 0; nf < 4; nf++)
#pragma unroll
            for (int c = 0; c < 4; c++) acc[mf][nf][c] = 0.f;

    auto fill = [&](int s, int st) {
        const int k0 = s * 32;
#pragma unroll
        for (int p = 0; p < 2; p++) {
            int k = (fsg + p * 2) << 3;
            uint32_t off = (uint32_t)st * VO_ST + ((fr * 40 + k) << 1);
            CP16(sb + off, g_h16 + (size_t)(m0 + fr) * H_ + k0 + k);
            CP16(sb + off + VO_B, g_wo_h + (size_t)(n0 + fr) * H_ + k0 + k);
        }
        CPCOMMIT();
    };

    fill(0, 0); fill(1, 1); fill(2, 2); fill(3, 3);
    for (int s = 0; s < 16; s++) {
        if (s <= 12) cp_wait<3>();
        else if (s == 13) cp_wait<2>();
        else if (s == 14) cp_wait<1>();
        else cp_wait<0>();
        __syncthreads();
        if (s + 4 < 16) fill(s + 4, (s + 4) % 5);
        const int buf = s % 5;
#pragma unroll
        for (int ks = 0; ks < 2; ks++) {
            uint32_t ah[4][4], bh[4][2];
#pragma unroll
            for (int mf = 0; mf < 4; mf++) {
                uint32_t roff = ((wm * 64 + mf * 16 + a_r) * 40 + ks * 16 + a_c) << 1;
                LDSM_X4(ah[mf][0], ah[mf][1], ah[mf][2], ah[mf][3],
                        sb + buf * VO_ST + roff);
            }
#pragma unroll
            for (int np = 0; np < 2; np++) {
                uint32_t roff = ((wn * 32 + np * 16 + b_r) * 40 + ks * 16 + b_c) << 1;
                LDSM_X4(bh[np * 2][0], bh[np * 2][1],
                        bh[np * 2 + 1][0], bh[np * 2 + 1][1],
                        sb + buf * VO_ST + VO_B + roff);
            }
#pragma unroll
            for (int mf = 0; mf < 4; mf++)
#pragma unroll
                for (int nf = 0; nf < 4; nf++) MMA_F16(acc[mf][nf], ah[mf], bh[nf]);
        }
    }
    float pm[8], ps_[8];
#pragma unroll
    for (int r = 0; r < 8; r++) { pm[r] = -1e30f; ps_[r] = 0.f; }
#pragma unroll
    for (int mf = 0; mf < 4; mf++) {
        int row = m0 + wm * 64 + mf * 16 + g;
#pragma unroll
        for (int nf = 0; nf < 4; nf++) {
            int col = n0 + wn * 32 + nf * 8 + q * 2;
            float b0 = bias[col], b1 = bias[col + 1];
            float v0 = acc[mf][nf][0] + b0, v1 = acc[mf][nf][1] + b1;
            float v2 = acc[mf][nf][2] + b0, v3 = acc[mf][nf][3] + b1;
            out[(size_t)row * V_ + col] = v0;
            out[(size_t)row * V_ + col + 1] = v1;
            out[(size_t)(row + 8) * V_ + col] = v2;
            out[(size_t)(row + 8) * V_ + col + 1] = v3;
            onl(pm[mf * 2], ps_[mf * 2], v0);
            onl(pm[mf * 2], ps_[mf * 2], v1);
            onl(pm[mf * 2 + 1], ps_[mf * 2 + 1], v2);
            onl(pm[mf * 2 + 1], ps_[mf * 2 + 1], v3);
        }
    }
    float* pmS = (float*)dsm;
    float* psS = (float*)(dsm + 128 * 17 * 4);
    __syncthreads();
#pragma unroll
    for (int mf = 0; mf < 4; mf++) {
#pragma unroll
        for (int half = 0; half < 2; half++) {
            int r = wm * 64 + mf * 16 + g + half * 8;
            pmS[r * 17 + wn * 4 + q] = pm[mf * 2 + half];
            psS[r * 17 + wn * 4 + q] = ps_[mf * 2 + half];
        }
    }
    __syncthreads();
    if (tid < 128) {
        float M = -1e30f, S = 0.f;
#pragma unroll
        for (int x = 0; x < 16; x++) {
            float m2 = pmS[tid * 17 + x], s2 = psS[tid * 17 + x];
            float Mn = fmaxf(M, m2);
            S = S * expf(M - Mn) + s2 * expf(m2 - Mn);
            M = Mn;
        }
        g_pm[(size_t)(m0 + tid) * NB_ + nb] = M;
        g_ps[(size_t)(m0 + tid) * NB_ + nb] = S;
    }
}

// ---------------------------------------------------------------------------
// K8: vocab softmax pass 2
// ---------------------------------------------------------------------------
__global__ __launch_bounds__(256) void k_sm2(const float* __restrict__ out,
                                             float* __restrict__ probs) {
    const int c = blockIdx.x, b = blockIdx.y, t = threadIdx.x;
    __shared__ float rm[256], rs[256];
    float m = -1e30f, s = 0.f;
    for (int j = t; j < NB_; j += 256) {
        float m2 = g_pm[(size_t)b * NB_ + j], s2 = g_ps[(size_t)b * NB_ + j];
        float Mn = fmaxf(m, m2);
        s = s * expf(m - Mn) + s2 * expf(m2 - Mn);
        m = Mn;
    }
    rm[t] = m; rs[t] = s;
    __syncthreads();
    for (int st = 128; st > 0; st >>= 1) {
        if (t < st) {
            float m2 = rm[t + st], s2 = rs[t + st];
            float M = fmaxf(rm[t], m2);
            rs[t] = rs[t] * expf(rm[t] - M) + s2 * expf(m2 - M);
            rm[t] = M;
        }
        __syncthreads();
    }
    const float M = rm[0], inv = 1.0f / rs[0];
    const float* row = out + (size_t)b * V_ + c * 4000;
    float* prow = probs + (size_t)b * V_ + c * 4000;
    for (int i = t; i < 4000; i += 256)
        prow[i] = expf(row[i] - M) * inv;
}

// ---------------------------------------------------------------------------
extern "C" void kernel_launch(void* const* d_in, const int* in_sizes, int n_in,
                              void* d_out, int out_size) {
    const float* tok  = (const float*)d_in[0];
    const float* hid  = (const float*)d_in[1];
    const float* cell = (const float*)d_in[2];
    const float* img  = (const float*)d_in[3];
    const float* Whw  = (const float*)d_in[4];
    const float* Whb  = (const float*)d_in[5];
    const float* Wfw  = (const float*)d_in[6];
    const float* Wfb  = (const float*)d_in[7];
    const float* Wih  = (const float*)d_in[8];
    const float* bih  = (const float*)d_in[9];
    const float* Whh  = (const float*)d_in[10];
    const float* bhh  = (const float*)d_in[11];
    const float* Wow  = (const float*)d_in[12];
    const float* Wob  = (const float*)d_in[13];

    float* out    = (float*)d_out;
    float* probs  = out;
    float* hnew   = out + (size_t)B_ * V_;
    float* cnew   = hnew + (size_t)B_ * H_;
    float* output = cnew + (size_t)B_ * H_;

    static cudaStream_t s1 = nullptr;
    static cudaEvent_t e0, e_pm, e_ht, e_ps, e_at, e_g02;
    if (!s1) {
        cudaStreamCreateWithFlags(&s1, cudaStreamNonBlocking);
        cudaEventCreateWithFlags(&e0, cudaEventDisableTiming);
        cudaEventCreateWithFlags(&e_pm, cudaEventDisableTiming);
        cudaEventCreateWithFlags(&e_ht, cudaEventDisableTiming);
        cudaEventCreateWithFlags(&e_ps, cudaEventDisableTiming);
        cudaEventCreateWithFlags(&e_at, cudaEventDisableTiming);
        cudaEventCreateWithFlags(&e_g02, cudaEventDisableTiming);
        cudaFuncSetAttribute(k_attn_f16, cudaFuncAttributeMaxDynamicSharedMemorySize, AT_SMEM);
        cudaFuncSetAttribute(k_gates_f16, cudaFuncAttributeMaxDynamicSharedMemorySize, GA_SMEM);
        cudaFuncSetAttribute(k_out_f16, cudaFuncAttributeMaxDynamicSharedMemorySize, VO_SMEM);
    }

    // Fork: ht (compute-bound) on s1 under prep_main (DRAM-bound).
    cudaEventRecord(e0, 0);
    cudaStreamWaitEvent(s1, e0, 0);
    k_ht<<<dim3(8, 4), 256, 0, s1>>>(hid, Whw, Whb, Wfb);
    cudaEventRecord(e_ht, s1);

    // Main: attn dependencies only.
    k_prep_main<<<(N_PREPM + 255) / 256, 256>>>(img, Wfw);
    cudaEventRecord(e_pm, 0);

    // Side preps (Wc/Wo/x-tokhid) gated after prep_main, drain under attn.
    cudaStreamWaitEvent(s1, e_pm, 0);
    k_prep_side<<<(N_PREPS + 255) / 256, 256, 0, s1>>>(Wih, Whh, Wow, tok, hid);
    cudaEventRecord(e_ps, s1);

    // Main chain: attn.
    cudaStreamWaitEvent(0, e_ht, 0);
    k_attn_f16<<<dim3(2, B_, 4), 256, AT_SMEM>>>();
    cudaEventRecord(e_at, 0);

    // Side: gates K-slices {tok, hid} (no ctx dep), concurrent with k_ctx.
    cudaStreamWaitEvent(s1, e_at, 0);
    k_gates_f16<<<dim3(16, 4, 2), 256, GA_SMEM, s1>>>(0, 1024);
    cudaEventRecord(e_g02, s1);

    // Main: ctx (writes xh/xl ctx slice), then gates K-slice {ctx}.
    k_ctx<<<dim3(8, B_), 256>>>();
    k_gates_f16<<<dim3(16, 4, 1), 256, GA_SMEM>>>(512, 0);
    cudaStreamWaitEvent(0, e_g02, 0);
    k_lstm<<<(B_ * H_ + 255) / 256, 256>>>(cell, bih, bhh, hnew, cnew);
    k_out_f16<<<dim3(NB_, 2), 256, VO_SMEM>>>(Wob, output);
    k_sm2<<<dim3(8, B_), 256>>>(output, probs);
}